// round 4
// baseline (speedup 1.0000x reference)
#include <cuda_runtime.h>
#include <cstdint>
#include <cstddef>

// Problem constants
#define BATCH 256
#define ANUM  128
#define NBNUM 256
#define DNUM  16
#define FA    64
#define FB    32
#define FPC   256
#define R_NEI  (BATCH*ANUM*DNUM)   // 524288
#define R_ATOM (BATCH*ANUM)        // 32768
#define R_BOND (BATCH*NBNUM)       // 65536
#define ATOM_OUT_ELEMS ((long long)R_ATOM*FPC)
#define NEI_OUT_ELEMS  ((long long)R_NEI*FPC)
#define BN_EPS 1e-6f
#define SLOPE  0.01f

// ---------------- device scratch ----------------
__device__ float g_P[(size_t)R_ATOM * FPC];   // 33.5 MB
__device__ float g_Q[(size_t)R_BOND * FPC];   // 67 MB
__device__ float g_cntA[R_ATOM];
__device__ float g_cntB[R_BOND];
__device__ float g_Sx[64*64];    // unweighted atom 2nd moment
__device__ float g_mx[64];       // unweighted atom 1st moment
__device__ float g_Saa[64*64];   // count-weighted atom moment
__device__ float g_Ma[64];
__device__ float g_Sbb[32*32];   // count-weighted bond moment
__device__ float g_Mb[32];
__device__ float g_Sab[64*32];   // cross moment over pairs
__device__ float g_scale[2][FPC];
__device__ float g_shift[2][FPC];

__global__ void zero_kernel() {
    int i = blockIdx.x * blockDim.x + threadIdx.x;
    if (i < R_ATOM) g_cntA[i] = 0.f;
    if (i < R_BOND) g_cntB[i] = 0.f;
    if (i < 64*64) { g_Sx[i] = 0.f; g_Saa[i] = 0.f; }
    if (i < 64*32) g_Sab[i] = 0.f;
    if (i < 32*32) g_Sbb[i] = 0.f;
    if (i < 64)    { g_mx[i] = 0.f; g_Ma[i] = 0.f; }
    if (i < 32)    g_Mb[i] = 0.f;
}

// ---------------- neighbor-count histograms ----------------
__global__ void count_kernel(const int* __restrict__ nl, const int* __restrict__ bl) {
    int r = blockIdx.x * blockDim.x + threadIdx.x;
    int stride = gridDim.x * blockDim.x;
    for (; r < R_NEI; r += stride) {
        int b = r >> 11;
        atomicAdd(&g_cntA[(b << 7) + nl[r]], 1.f);
        atomicAdd(&g_cntB[(b << 8) + bl[r]], 1.f);
    }
}

// ---------------- (weighted) feature moments: S = X^T diag(w) X, M = X^T w -
template<int F, bool WEIGHTED>
__global__ __launch_bounds__(256)
void moments_kernel(const float4* __restrict__ X, const float* __restrict__ cnt,
                    float* __restrict__ S, float* __restrict__ M, int R)
{
    __shared__ float xs[32][F];
    __shared__ float cw[32];
    constexpr int FQ = F / 4;
    constexpr int TI = (F == 64) ? 4 : 2;
    const int tid = threadIdx.x;
    const int i0 = (tid >> 4) * TI;
    const int j0 = (tid & 15) * TI;

    float acc[TI][TI];
    #pragma unroll
    for (int a = 0; a < TI; ++a)
        #pragma unroll
        for (int b = 0; b < TI; ++b) acc[a][b] = 0.f;
    float mp[TI];
    #pragma unroll
    for (int a = 0; a < TI; ++a) mp[a] = 0.f;

    const int rowsPerBlock = R / gridDim.x;
    const int base = blockIdx.x * rowsPerBlock;

    for (int s = 0; s < rowsPerBlock; s += 32) {
        for (int idx = tid; idx < 32 * FQ; idx += 256) {
            int row = idx / FQ, q = idx % FQ;
            float4 v = X[(size_t)(base + s + row) * FQ + q];
            *(float4*)&xs[row][q * 4] = v;
        }
        if (tid < 32) cw[tid] = WEIGHTED ? cnt[base + s + tid] : 1.f;
        __syncthreads();
        for (int k = 0; k < 32; ++k) {
            float c = cw[k];
            float xi[TI], xj[TI];
            #pragma unroll
            for (int a = 0; a < TI; ++a) { xi[a] = xs[k][i0 + a] * c; xj[a] = xs[k][j0 + a]; }
            #pragma unroll
            for (int a = 0; a < TI; ++a)
                #pragma unroll
                for (int b = 0; b < TI; ++b) acc[a][b] += xi[a] * xj[b];
            if ((tid >> 4) == 0) {
                #pragma unroll
                for (int b = 0; b < TI; ++b) mp[b] += c * xj[b];
            }
        }
        __syncthreads();
    }
    #pragma unroll
    for (int a = 0; a < TI; ++a)
        #pragma unroll
        for (int b = 0; b < TI; ++b)
            atomicAdd(&S[(i0 + a) * F + (j0 + b)], acc[a][b]);
    if ((tid >> 4) == 0) {
        #pragma unroll
        for (int b = 0; b < TI; ++b) atomicAdd(&M[j0 + b], mp[b]);
    }
}

// ---------------- cross moment: Sab = sum_r A[na_r] B[nb_r]^T ------------
__global__ __launch_bounds__(256)
void sab_kernel(const float4* __restrict__ A, const float4* __restrict__ B,
                const int* __restrict__ nl, const int* __restrict__ bl)
{
    __shared__ float as[64][64];
    __shared__ float bs[64][32];
    __shared__ int ias[64], ibs[64];
    const int tid = threadIdx.x;
    const int i0 = (tid >> 3) * 2;   // a-dim, 0..62
    const int j0 = (tid & 7) * 4;    // b-dim, 0..28
    float acc[2][4] = {{0,0,0,0},{0,0,0,0}};

    const int rowsPerBlock = R_NEI / gridDim.x;
    const int base = blockIdx.x * rowsPerBlock;

    for (int s = 0; s < rowsPerBlock; s += 64) {
        if (tid < 64) {
            int gr = base + s + tid;
            ias[tid] = ((gr >> 11) << 7) + nl[gr];
        } else if (tid < 128) {
            int gr = base + s + tid - 64;
            ibs[tid - 64] = ((gr >> 11) << 8) + bl[gr];
        }
        __syncthreads();
        for (int idx = tid; idx < 1024; idx += 256) {
            int row = idx >> 4, q = idx & 15;
            float4 v = A[(size_t)ias[row] * 16 + q];
            *(float4*)&as[row][q * 4] = v;
        }
        for (int idx = tid; idx < 512; idx += 256) {
            int row = idx >> 3, q = idx & 7;
            float4 v = B[(size_t)ibs[row] * 8 + q];
            *(float4*)&bs[row][q * 4] = v;
        }
        __syncthreads();
        #pragma unroll 4
        for (int k = 0; k < 64; ++k) {
            float2 a = *(const float2*)&as[k][i0];
            float4 b = *(const float4*)&bs[k][j0];
            acc[0][0] += a.x * b.x; acc[0][1] += a.x * b.y;
            acc[0][2] += a.x * b.z; acc[0][3] += a.x * b.w;
            acc[1][0] += a.y * b.x; acc[1][1] += a.y * b.y;
            acc[1][2] += a.y * b.z; acc[1][3] += a.y * b.w;
        }
        __syncthreads();
    }
    #pragma unroll
    for (int a = 0; a < 2; ++a)
        #pragma unroll
        for (int b = 0; b < 4; ++b)
            atomicAdd(&g_Sab[(i0 + a) * 32 + (j0 + b)], acc[a][b]);
}

// ---------------- finalize: scale/shift from analytic moments ------------
__global__ void finalize_kernel(const float* __restrict__ atom_W,
                                const float* __restrict__ atom_gamma,
                                const float* __restrict__ atom_beta,
                                const float* __restrict__ nei_W,
                                const float* __restrict__ nei_gamma,
                                const float* __restrict__ nei_beta)
{
    __shared__ float w[96];
    __shared__ float red[128], red2[128];
    const int c = blockIdx.x;          // 0..255 nei, 256..511 atom
    const int t = threadIdx.x;         // 128 threads
    const bool isNei = c < 256;
    const int ch = isNei ? c : c - 256;
    const int dim = isNei ? 96 : 64;
    const float* W = isNei ? nei_W : atom_W;
    if (t < dim) w[t] = W[ch * dim + t];
    __syncthreads();

    float wv = 0.f, wm = 0.f;
    if (t < dim) {
        float v = 0.f;
        if (isNei) {
            if (t < 64) {
                for (int j = 0; j < 64; ++j) v += g_Saa[t*64 + j] * w[j];
                for (int j = 0; j < 32; ++j) v += g_Sab[t*32 + j] * w[64 + j];
                wm = w[t] * g_Ma[t];
            } else {
                int ii = t - 64;
                for (int j = 0; j < 64; ++j) v += g_Sab[j*32 + ii] * w[j];
                for (int j = 0; j < 32; ++j) v += g_Sbb[ii*32 + j] * w[64 + j];
                wm = w[t] * g_Mb[ii];
            }
        } else {
            for (int j = 0; j < 64; ++j) v += g_Sx[t*64 + j] * w[j];
            wm = w[t] * g_mx[t];
        }
        wv = w[t] * v;
    }
    red[t] = wv; red2[t] = wm;
    __syncthreads();
    for (int s = 64; s > 0; s >>= 1) {
        if (t < s) { red[t] += red[t + s]; red2[t] += red2[t + s]; }
        __syncthreads();
    }
    if (t == 0) {
        float n = isNei ? (float)R_NEI : (float)R_ATOM;
        float mean = red2[0] / n;                    // mean of t = W.x (bias cancels)
        float var  = red[0] / n - mean * mean;
        const float* G  = isNei ? nei_gamma : atom_gamma;
        const float* Bt = isNei ? nei_beta  : atom_beta;
        float sc = G[ch] * rsqrtf(var + BN_EPS);
        int si = isNei ? 1 : 0;
        g_scale[si][ch] = sc;
        g_shift[si][ch] = Bt[ch] - mean * sc;
    }
}

// ---------------- packed f32x2 helpers ----------------
__device__ __forceinline__ unsigned long long pack2(float lo, float hi) {
    unsigned long long r;
    asm("mov.b64 %0, {%1,%2};" : "=l"(r) : "f"(lo), "f"(hi));
    return r;
}
__device__ __forceinline__ void fma2(unsigned long long& d,
                                     unsigned long long a,
                                     unsigned long long b) {
    asm("fma.rn.f32x2 %0, %1, %2, %0;" : "+l"(d) : "l"(a), "l"(b));
}
__device__ __forceinline__ float2 unpack2(unsigned long long v) {
    float2 r;
    asm("mov.b64 {%0,%1}, %2;" : "=f"(r.x), "=f"(r.y) : "l"(v));
    return r;
}

// ---------------- dense GEMM: out[r][c] = W[c] . X[r]  (opt. fused BN) ---
// 64 rows x 256 ch per block, 256 threads, 8x8 per thread, 2 CTAs/SM.
template<int K, bool NORM>
__global__ __launch_bounds__(256, 2)
void gemm_kernel(const float4* __restrict__ Wg, int wldq, int woffq,
                 const float4* __restrict__ X,
                 float* __restrict__ out, int numTiles)
{
    extern __shared__ float smem[];
    constexpr int KQ = K / 4;
    float* ws = smem;               // K*256
    float* xs = smem + K * FPC;     // K*64

    const int tid = threadIdx.x;
    const int r0 = (tid >> 5) * 8;
    const int c0 = (tid & 31) * 8;

    for (int idx = tid; idx < FPC * KQ; idx += 256) {
        int q = idx >> 8;
        int c = idx & 255;
        float4 v = Wg[(size_t)c * wldq + woffq + q];
        ws[(4*q+0)*FPC + c] = v.x;
        ws[(4*q+1)*FPC + c] = v.y;
        ws[(4*q+2)*FPC + c] = v.z;
        ws[(4*q+3)*FPC + c] = v.w;
    }

    float scv[8], shv[8];
    if (NORM) {
        #pragma unroll
        for (int j = 0; j < 8; ++j) {
            scv[j] = g_scale[0][c0 + j];
            shv[j] = g_shift[0][c0 + j];
        }
    }
    __syncthreads();

    for (int tile = blockIdx.x; tile < numTiles; tile += gridDim.x) {
        for (int idx = tid; idx < 64 * KQ; idx += 256) {
            int lr = idx & 63;
            int q  = idx >> 6;
            float4 v = X[(size_t)(tile * 64 + lr) * KQ + q];
            xs[(4*q+0)*64 + lr] = v.x;
            xs[(4*q+1)*64 + lr] = v.y;
            xs[(4*q+2)*64 + lr] = v.z;
            xs[(4*q+3)*64 + lr] = v.w;
        }
        __syncthreads();

        unsigned long long acc[8][4];
        #pragma unroll
        for (int i = 0; i < 8; ++i)
            #pragma unroll
            for (int j = 0; j < 4; ++j) acc[i][j] = 0ull;

        #pragma unroll 2
        for (int k = 0; k < K; ++k) {
            const float4 xa = *(const float4*)&xs[k*64 + r0];
            const float4 xb = *(const float4*)&xs[k*64 + r0 + 4];
            const ulonglong2 w0 = *(const ulonglong2*)&ws[k*FPC + c0];
            const ulonglong2 w1 = *(const ulonglong2*)&ws[k*FPC + c0 + 4];
            unsigned long long xp[8];
            xp[0] = pack2(xa.x, xa.x); xp[1] = pack2(xa.y, xa.y);
            xp[2] = pack2(xa.z, xa.z); xp[3] = pack2(xa.w, xa.w);
            xp[4] = pack2(xb.x, xb.x); xp[5] = pack2(xb.y, xb.y);
            xp[6] = pack2(xb.z, xb.z); xp[7] = pack2(xb.w, xb.w);
            #pragma unroll
            for (int i = 0; i < 8; ++i) {
                fma2(acc[i][0], xp[i], w0.x);
                fma2(acc[i][1], xp[i], w0.y);
                fma2(acc[i][2], xp[i], w1.x);
                fma2(acc[i][3], xp[i], w1.y);
            }
        }

        #pragma unroll
        for (int i = 0; i < 8; ++i) {
            float y[8];
            #pragma unroll
            for (int j = 0; j < 4; ++j) {
                float2 p = unpack2(acc[i][j]);
                y[2*j]   = p.x;
                y[2*j+1] = p.y;
            }
            if (NORM) {
                #pragma unroll
                for (int j = 0; j < 8; ++j) {
                    y[j] = y[j] * scv[j] + shv[j];
                    y[j] = fmaxf(y[j], SLOPE * y[j]);
                }
            }
            size_t row = (size_t)tile * 64 + r0 + i;
            float4* o = (float4*)&out[row * FPC + c0];
            o[0] = make_float4(y[0], y[1], y[2], y[3]);
            o[1] = make_float4(y[4], y[5], y[6], y[7]);
        }
        __syncthreads();
    }
}

// ---------------- nei output: smem-cached P/Q halves per batch -----------
// block = (batch, channel-half). smem: P half 64KB + Q half 128KB + idx 16KB.
__global__ __launch_bounds__(512, 1)
void nei_out_kernel(const int* __restrict__ nl, const int* __restrict__ bl,
                    float* __restrict__ out)
{
    extern __shared__ float4 sm4[];
    float4* ps = sm4;                     // 128*32
    float4* qs = sm4 + 128*32;            // 256*32
    int2*   idx = (int2*)(qs + 256*32);   // 2048

    const int tid  = threadIdx.x;
    const int b    = blockIdx.x >> 1;
    const int half = blockIdx.x & 1;
    const int lane = tid & 31;
    const int warp = tid >> 5;

    const float4* P4 = (const float4*)g_P;
    const float4* Q4 = (const float4*)g_Q;

    for (int i = tid; i < 128*32; i += 512) {
        int a = i >> 5, q = i & 31;
        ps[i] = P4[(size_t)(b*128 + a)*64 + half*32 + q];
    }
    for (int i = tid; i < 256*32; i += 512) {
        int bd = i >> 5, q = i & 31;
        qs[i] = Q4[(size_t)(b*256 + bd)*64 + half*32 + q];
    }
    for (int i = tid; i < 2048; i += 512) {
        int r = b*2048 + i;
        idx[i] = make_int2(nl[r], bl[r]);
    }
    float4 s = ((const float4*)g_scale[1])[half*32 + lane];
    float4 h = ((const float4*)g_shift[1])[half*32 + lane];
    __syncthreads();

    for (int row = warp; row < 2048; row += 16) {
        int2 ab = idx[row];
        float4 p = ps[ab.x * 32 + lane];
        float4 q = qs[ab.y * 32 + lane];
        float4 v;
        v.x = (p.x + q.x) * s.x + h.x;
        v.y = (p.y + q.y) * s.y + h.y;
        v.z = (p.z + q.z) * s.z + h.z;
        v.w = (p.w + q.w) * s.w + h.w;
        v.x = fmaxf(v.x, SLOPE * v.x);
        v.y = fmaxf(v.y, SLOPE * v.y);
        v.z = fmaxf(v.z, SLOPE * v.z);
        v.w = fmaxf(v.w, SLOPE * v.w);
        *(float4*)&out[(size_t)(b*2048 + row)*256 + half*128 + lane*4] = v;
    }
}

// ---------------- launcher ------------------------------------------------
extern "C" void kernel_launch(void* const* d_in, const int* in_sizes, int n_in,
                              void* d_out, int out_size) {
    const float* atom_features = (const float*)d_in[0];
    const float* bond_features = (const float*)d_in[1];
    const int*   atom_nl       = (const int*)  d_in[2];
    const int*   bond_nl       = (const int*)  d_in[3];
    const float* atom_W        = (const float*)d_in[4];
    const float* atom_gamma    = (const float*)d_in[6];
    const float* atom_beta     = (const float*)d_in[7];
    const float* nei_W         = (const float*)d_in[8];
    const float* nei_gamma     = (const float*)d_in[10];
    const float* nei_beta      = (const float*)d_in[11];

    float* out_atom = (float*)d_out;
    float* out_nei  = (float*)d_out + ATOM_OUT_ELEMS;

    float *pP = nullptr, *pQ = nullptr;
    cudaGetSymbolAddress((void**)&pP, g_P);
    cudaGetSymbolAddress((void**)&pQ, g_Q);
    float *pCA = nullptr, *pCB = nullptr;
    cudaGetSymbolAddress((void**)&pCA, g_cntA);
    cudaGetSymbolAddress((void**)&pCB, g_cntB);
    float *pSx, *pmx, *pSaa, *pMa, *pSbb, *pMb;
    cudaGetSymbolAddress((void**)&pSx,  g_Sx);
    cudaGetSymbolAddress((void**)&pmx,  g_mx);
    cudaGetSymbolAddress((void**)&pSaa, g_Saa);
    cudaGetSymbolAddress((void**)&pMa,  g_Ma);
    cudaGetSymbolAddress((void**)&pSbb, g_Sbb);
    cudaGetSymbolAddress((void**)&pMb,  g_Mb);

    const int smem64 = (64*FPC + 64*64) * (int)sizeof(float);   // 81920
    const int smem32 = (32*FPC + 32*64) * (int)sizeof(float);   // 40960
    const int smemNO = (128*32 + 256*32) * 16 + 2048 * 8;       // 212992
    cudaFuncSetAttribute((const void*)gemm_kernel<64, true>,
                         cudaFuncAttributeMaxDynamicSharedMemorySize, smem64);
    cudaFuncSetAttribute((const void*)gemm_kernel<64, false>,
                         cudaFuncAttributeMaxDynamicSharedMemorySize, smem64);
    cudaFuncSetAttribute((const void*)gemm_kernel<32, false>,
                         cudaFuncAttributeMaxDynamicSharedMemorySize, smem32);
    cudaFuncSetAttribute((const void*)nei_out_kernel,
                         cudaFuncAttributeMaxDynamicSharedMemorySize, smemNO);

    // 1) zero scratch moments/counts
    zero_kernel<<<256, 256>>>();

    // 2) neighbor-count histograms
    count_kernel<<<512, 256>>>(atom_nl, bond_nl);

    // 3) analytic feature moments
    moments_kernel<64, false><<<128, 256>>>((const float4*)atom_features, nullptr,
                                            pSx, pmx, R_ATOM);
    moments_kernel<64, true ><<<128, 256>>>((const float4*)atom_features, pCA,
                                            pSaa, pMa, R_ATOM);
    moments_kernel<32, true ><<<128, 256>>>((const float4*)bond_features, pCB,
                                            pSbb, pMb, R_BOND);

    // 4) cross moment over gathered pairs
    sab_kernel<<<512, 256>>>((const float4*)atom_features,
                             (const float4*)bond_features, atom_nl, bond_nl);

    // 5) P = A @ Wa^T, Q = B @ Wb^T (raw, no bias — bias cancels in BN)
    gemm_kernel<64, false><<<512, 256, smem64>>>(
        (const float4*)nei_W, 24, 0, (const float4*)atom_features, pP, R_ATOM / 64);
    gemm_kernel<32, false><<<592, 256, smem32>>>(
        (const float4*)nei_W, 24, 16, (const float4*)bond_features, pQ, R_BOND / 64);

    // 6) per-channel scale/shift from analytic stats
    finalize_kernel<<<512, 128>>>(atom_W, atom_gamma, atom_beta,
                                  nei_W, nei_gamma, nei_beta);

    // 7) atom branch: GEMM with fused normalize + leaky (single write)
    gemm_kernel<64, true><<<512, 256, smem64>>>(
        (const float4*)atom_W, 16, 0, (const float4*)atom_features,
        out_atom, R_ATOM / 64);

    // 8) nei output: smem-cached P/Q, fused normalize + leaky, single write
    nei_out_kernel<<<512, 512, smemNO>>>(atom_nl, bond_nl, out_nei);
}

// round 5
// speedup vs baseline: 1.0987x; 1.0987x over previous
#include <cuda_runtime.h>
#include <cstdint>
#include <cstddef>

#define BATCH 256
#define ANUM  128
#define NBNUM 256
#define DNUM  16
#define FA    64
#define FB    32
#define FPC   256
#define R_NEI  (BATCH*ANUM*DNUM)   // 524288
#define R_ATOM (BATCH*ANUM)        // 32768
#define R_BOND (BATCH*NBNUM)       // 65536
#define ATOM_OUT_ELEMS ((long long)R_ATOM*FPC)
#define NEI_OUT_ELEMS  ((long long)R_NEI*FPC)
#define BN_EPS 1e-6f
#define SLOPE  0.01f

// ---------------- device scratch ----------------
__device__ float g_P[(size_t)R_ATOM * FPC];   // 33.5 MB
__device__ float g_Q[(size_t)R_BOND * FPC];   // 67 MB
__device__ float g_cntA[R_ATOM];
__device__ float g_cntB[R_BOND];
__device__ float g_Sab[64*32];                // cross moment over pairs
__device__ float g_sum[2][FPC];
__device__ float g_sqsum[2][FPC];
__device__ float g_scale[2][FPC];
__device__ float g_shift[2][FPC];

__global__ void zero_kernel() {
    int i = blockIdx.x * blockDim.x + threadIdx.x;
    if (i < 64*32) g_Sab[i] = 0.f;
    if (i < FPC) {
        g_sum[0][i] = 0.f; g_sum[1][i] = 0.f;
        g_sqsum[0][i] = 0.f; g_sqsum[1][i] = 0.f;
    }
}

// ---------------- per-batch neighbor-count histograms (no global atomics) -
__global__ __launch_bounds__(256)
void count_kernel(const int* __restrict__ nl, const int* __restrict__ bl) {
    __shared__ float hA[ANUM];
    __shared__ float hB[NBNUM];
    const int tid = threadIdx.x;
    const int b = blockIdx.x;
    if (tid < ANUM) hA[tid] = 0.f;
    hB[tid] = 0.f;
    __syncthreads();
    const int base = b * (ANUM * DNUM);
    for (int i = tid; i < ANUM * DNUM; i += 256) {
        atomicAdd(&hA[nl[base + i]], 1.f);
        atomicAdd(&hB[bl[base + i]], 1.f);
    }
    __syncthreads();
    if (tid < ANUM) g_cntA[b * ANUM + tid] = hA[tid];
    g_cntB[b * NBNUM + tid] = hB[tid];
}

// ---------------- cross moment: Sab = sum_r A[na_r] B[nb_r]^T ------------
__global__ __launch_bounds__(256)
void sab_kernel(const float4* __restrict__ A, const float4* __restrict__ B,
                const int* __restrict__ nl, const int* __restrict__ bl)
{
    __shared__ float as[64][64];
    __shared__ float bs[64][32];
    __shared__ int ias[64], ibs[64];
    const int tid = threadIdx.x;
    const int i0 = (tid >> 3) * 2;
    const int j0 = (tid & 7) * 4;
    float acc[2][4] = {{0,0,0,0},{0,0,0,0}};

    const int rowsPerBlock = R_NEI / gridDim.x;
    const int base = blockIdx.x * rowsPerBlock;

    for (int s = 0; s < rowsPerBlock; s += 64) {
        if (tid < 64) {
            int gr = base + s + tid;
            ias[tid] = ((gr >> 11) << 7) + nl[gr];
        } else if (tid < 128) {
            int gr = base + s + tid - 64;
            ibs[tid - 64] = ((gr >> 11) << 8) + bl[gr];
        }
        __syncthreads();
        for (int idx = tid; idx < 1024; idx += 256) {
            int row = idx >> 4, q = idx & 15;
            float4 v = A[(size_t)ias[row] * 16 + q];
            *(float4*)&as[row][q * 4] = v;
        }
        for (int idx = tid; idx < 512; idx += 256) {
            int row = idx >> 3, q = idx & 7;
            float4 v = B[(size_t)ibs[row] * 8 + q];
            *(float4*)&bs[row][q * 4] = v;
        }
        __syncthreads();
        #pragma unroll 4
        for (int k = 0; k < 64; ++k) {
            float2 a = *(const float2*)&as[k][i0];
            float4 b = *(const float4*)&bs[k][j0];
            acc[0][0] += a.x * b.x; acc[0][1] += a.x * b.y;
            acc[0][2] += a.x * b.z; acc[0][3] += a.x * b.w;
            acc[1][0] += a.y * b.x; acc[1][1] += a.y * b.y;
            acc[1][2] += a.y * b.z; acc[1][3] += a.y * b.w;
        }
        __syncthreads();
    }
    #pragma unroll
    for (int a = 0; a < 2; ++a)
        #pragma unroll
        for (int b = 0; b < 4; ++b)
            atomicAdd(&g_Sab[(i0 + a) * 32 + (j0 + b)], acc[a][b]);
}

// ---------------- packed f32x2 helpers ----------------
__device__ __forceinline__ unsigned long long pack2(float lo, float hi) {
    unsigned long long r;
    asm("mov.b64 %0, {%1,%2};" : "=l"(r) : "f"(lo), "f"(hi));
    return r;
}
__device__ __forceinline__ void fma2(unsigned long long& d,
                                     unsigned long long a,
                                     unsigned long long b) {
    asm("fma.rn.f32x2 %0, %1, %2, %0;" : "+l"(d) : "l"(a), "l"(b));
}
__device__ __forceinline__ float2 unpack2(unsigned long long v) {
    float2 r;
    asm("mov.b64 {%0,%1}, %2;" : "=f"(r.x), "=f"(r.y) : "l"(v));
    return r;
}

// ---------------- dense GEMM: out[r][c] = W[c].X[r], opt stats epilogue --
// 64 rows x 256 ch per block, 256 threads, 8x8 per thread.
template<int K, bool STATS>
__global__ __launch_bounds__(256, 2)
void gemm_kernel(const float4* __restrict__ Wg, int wldq, int woffq,
                 const float4* __restrict__ X,
                 float* __restrict__ out, int numTiles)
{
    extern __shared__ float smem[];
    constexpr int KQ = K / 4;
    float* ws = smem;               // K*256
    float* xs = smem + K * FPC;     // K*64
    float* ssum = xs + K * 64;      // 256 (STATS)
    float* ssq  = ssum + FPC;       // 256

    const int tid = threadIdx.x;
    const int r0 = (tid >> 5) * 8;
    const int c0 = (tid & 31) * 8;

    for (int idx = tid; idx < FPC * KQ; idx += 256) {
        int q = idx >> 8;
        int c = idx & 255;
        float4 v = Wg[(size_t)c * wldq + woffq + q];
        ws[(4*q+0)*FPC + c] = v.x;
        ws[(4*q+1)*FPC + c] = v.y;
        ws[(4*q+2)*FPC + c] = v.z;
        ws[(4*q+3)*FPC + c] = v.w;
    }

    float sumc[8], sqc[8];
    if (STATS) {
        #pragma unroll
        for (int j = 0; j < 8; ++j) { sumc[j] = 0.f; sqc[j] = 0.f; }
    }
    __syncthreads();

    for (int tile = blockIdx.x; tile < numTiles; tile += gridDim.x) {
        for (int idx = tid; idx < 64 * KQ; idx += 256) {
            int lr = idx & 63;
            int q  = idx >> 6;
            float4 v = X[(size_t)(tile * 64 + lr) * KQ + q];
            xs[(4*q+0)*64 + lr] = v.x;
            xs[(4*q+1)*64 + lr] = v.y;
            xs[(4*q+2)*64 + lr] = v.z;
            xs[(4*q+3)*64 + lr] = v.w;
        }
        __syncthreads();

        unsigned long long acc[8][4];
        #pragma unroll
        for (int i = 0; i < 8; ++i)
            #pragma unroll
            for (int j = 0; j < 4; ++j) acc[i][j] = 0ull;

        #pragma unroll 2
        for (int k = 0; k < K; ++k) {
            const float4 xa = *(const float4*)&xs[k*64 + r0];
            const float4 xb = *(const float4*)&xs[k*64 + r0 + 4];
            const ulonglong2 w0 = *(const ulonglong2*)&ws[k*FPC + c0];
            const ulonglong2 w1 = *(const ulonglong2*)&ws[k*FPC + c0 + 4];
            unsigned long long xp[8];
            xp[0] = pack2(xa.x, xa.x); xp[1] = pack2(xa.y, xa.y);
            xp[2] = pack2(xa.z, xa.z); xp[3] = pack2(xa.w, xa.w);
            xp[4] = pack2(xb.x, xb.x); xp[5] = pack2(xb.y, xb.y);
            xp[6] = pack2(xb.z, xb.z); xp[7] = pack2(xb.w, xb.w);
            #pragma unroll
            for (int i = 0; i < 8; ++i) {
                fma2(acc[i][0], xp[i], w0.x);
                fma2(acc[i][1], xp[i], w0.y);
                fma2(acc[i][2], xp[i], w1.x);
                fma2(acc[i][3], xp[i], w1.y);
            }
        }

        #pragma unroll
        for (int i = 0; i < 8; ++i) {
            float y[8];
            #pragma unroll
            for (int j = 0; j < 4; ++j) {
                float2 p = unpack2(acc[i][j]);
                y[2*j]   = p.x;
                y[2*j+1] = p.y;
            }
            if (STATS) {
                #pragma unroll
                for (int j = 0; j < 8; ++j) { sumc[j] += y[j]; sqc[j] += y[j]*y[j]; }
            }
            size_t row = (size_t)tile * 64 + r0 + i;
            float4* o = (float4*)&out[row * FPC + c0];
            o[0] = make_float4(y[0], y[1], y[2], y[3]);
            o[1] = make_float4(y[4], y[5], y[6], y[7]);
        }
        __syncthreads();
    }

    if (STATS) {
        ssum[tid] = 0.f; ssq[tid] = 0.f;
        __syncthreads();
        #pragma unroll
        for (int j = 0; j < 8; ++j) {
            atomicAdd(&ssum[c0 + j], sumc[j]);
            atomicAdd(&ssq [c0 + j], sqc[j]);
        }
        __syncthreads();
        atomicAdd(&g_sum[0][tid],   ssum[tid]);
        atomicAdd(&g_sqsum[0][tid], ssq[tid]);
    }
}

// ---------------- weighted column sums of P and Q (nei 1st/2nd moments) --
// lane owns channels [lane*4,+4) and [128+lane*4,+4).
__global__ __launch_bounds__(256, 8)
void pq_stats_kernel() {
    __shared__ float ssum[FPC], ssq[FPC];
    const int tid = threadIdx.x;
    const int lane = tid & 31;
    const int gw = (blockIdx.x * blockDim.x + tid) >> 5;
    const int nw = (gridDim.x * blockDim.x) >> 5;

    float s1[8] = {0,0,0,0,0,0,0,0};
    float s2[8] = {0,0,0,0,0,0,0,0};

    for (int a = gw; a < R_ATOM; a += nw) {
        float c = g_cntA[a];
        const float4* prow = (const float4*)&g_P[(size_t)a * FPC];
        float4 p0 = prow[lane], p1 = prow[lane + 32];
        float t[8] = {p0.x, p0.y, p0.z, p0.w, p1.x, p1.y, p1.z, p1.w};
        #pragma unroll
        for (int j = 0; j < 8; ++j) { s1[j] += c * t[j]; s2[j] += c * t[j] * t[j]; }
    }
    for (int b = gw; b < R_BOND; b += nw) {
        float c = g_cntB[b];
        const float4* qrow = (const float4*)&g_Q[(size_t)b * FPC];
        float4 q0 = qrow[lane], q1 = qrow[lane + 32];
        float t[8] = {q0.x, q0.y, q0.z, q0.w, q1.x, q1.y, q1.z, q1.w};
        #pragma unroll
        for (int j = 0; j < 8; ++j) { s1[j] += c * t[j]; s2[j] += c * t[j] * t[j]; }
    }

    if (tid < FPC) { ssum[tid] = 0.f; ssq[tid] = 0.f; }
    __syncthreads();
    #pragma unroll
    for (int j = 0; j < 4; ++j) {
        atomicAdd(&ssum[lane*4 + j],       s1[j]);
        atomicAdd(&ssum[128 + lane*4 + j], s1[4+j]);
        atomicAdd(&ssq [lane*4 + j],       s2[j]);
        atomicAdd(&ssq [128 + lane*4 + j], s2[4+j]);
    }
    __syncthreads();
    if (tid < FPC) {
        atomicAdd(&g_sum[1][tid],   ssum[tid]);
        atomicAdd(&g_sqsum[1][tid], ssq[tid]);
    }
}

// ---------------- finalize: scale/shift --------------------------------
// blocks 0..255: nei channel (cross term via Sab); block 256: all atom ch.
__global__ void finalize_kernel(const float* __restrict__ atom_gamma,
                                const float* __restrict__ atom_beta,
                                const float* __restrict__ nei_W,
                                const float* __restrict__ nei_gamma,
                                const float* __restrict__ nei_beta)
{
    const int t = threadIdx.x;
    if (blockIdx.x == 256) {
        // atom branch: stats accumulated by GEMM epilogue
        float n = (float)R_ATOM;
        float mean = g_sum[0][t] / n;
        float var  = g_sqsum[0][t] / n - mean * mean;
        float sc = atom_gamma[t] * rsqrtf(var + BN_EPS);
        g_scale[0][t] = sc;
        g_shift[0][t] = atom_beta[t] - mean * sc;
        return;
    }
    const int c = blockIdx.x;
    __shared__ float wB_s[32];
    __shared__ float red[64];
    if (t < 32) wB_s[t] = nei_W[c * 96 + 64 + t];
    __syncthreads();
    if (t < 64) {
        float v = 0.f;
        #pragma unroll
        for (int j = 0; j < 32; ++j) v += g_Sab[t * 32 + j] * wB_s[j];
        red[t] = v * nei_W[c * 96 + t];
    }
    __syncthreads();
    if (t == 0) {
        float cross = 0.f;
        #pragma unroll
        for (int j = 0; j < 64; ++j) cross += red[j];
        float n = (float)R_NEI;
        float mean = g_sum[1][c] / n;
        float var  = (g_sqsum[1][c] + 2.f * cross) / n - mean * mean;
        float sc = nei_gamma[c] * rsqrtf(var + BN_EPS);
        g_scale[1][c] = sc;
        g_shift[1][c] = nei_beta[c] - mean * sc;
    }
}

// ---------------- atom normalize + leaky (in place) ----------------------
__global__ void norm_leaky_kernel(float4* __restrict__ data, long long n4) {
    const float4* sc4 = (const float4*)g_scale[0];
    const float4* sh4 = (const float4*)g_shift[0];
    long long i = (long long)blockIdx.x * blockDim.x + threadIdx.x;
    long long stride = (long long)gridDim.x * blockDim.x;
    for (; i < n4; i += stride) {
        float4 v = data[i];
        int cq = (int)(i & 63);
        float4 s = sc4[cq];
        float4 h = sh4[cq];
        v.x = v.x * s.x + h.x;  v.y = v.y * s.y + h.y;
        v.z = v.z * s.z + h.z;  v.w = v.w * s.w + h.w;
        v.x = fmaxf(v.x, SLOPE * v.x);
        v.y = fmaxf(v.y, SLOPE * v.y);
        v.z = fmaxf(v.z, SLOPE * v.z);
        v.w = fmaxf(v.w, SLOPE * v.w);
        data[i] = v;
    }
}

// ---------------- nei output: smem-cached P/Q channel-quarters -----------
// block = (batch, quarter): P 32KB + Q 64KB + packed idx 8KB = 104KB, 2/SM.
__global__ __launch_bounds__(512, 2)
void nei_out_kernel(const int* __restrict__ nl, const int* __restrict__ bl,
                    float* __restrict__ out)
{
    extern __shared__ float4 sm4[];
    float4* ps = sm4;                     // 128*16
    float4* qs = sm4 + 128*16;            // 256*16
    int*    sidx = (int*)(qs + 256*16);   // 2048

    const int tid  = threadIdx.x;
    const int b    = blockIdx.x >> 2;
    const int qt   = blockIdx.x & 3;
    const int lane = tid & 31;
    const int warp = tid >> 5;
    const int c16  = lane & 15;

    const float4* P4 = (const float4*)g_P;
    const float4* Q4 = (const float4*)g_Q;

    for (int i = tid; i < 128*16; i += 512) {
        int a = i >> 4, q = i & 15;
        ps[i] = P4[(size_t)(b*128 + a)*64 + qt*16 + q];
    }
    for (int i = tid; i < 256*16; i += 512) {
        int bd = i >> 4, q = i & 15;
        qs[i] = Q4[(size_t)(b*256 + bd)*64 + qt*16 + q];
    }
    for (int i = tid; i < 2048; i += 512) {
        int r = b*2048 + i;
        sidx[i] = nl[r] | (bl[r] << 8);
    }
    float4 s = ((const float4*)g_scale[1])[qt*16 + c16];
    float4 h = ((const float4*)g_shift[1])[qt*16 + c16];
    __syncthreads();

    // each warp handles 2 rows per iteration (half-warp per row)
    for (int rp = warp; rp < 1024; rp += 16) {
        int row = rp * 2 + (lane >> 4);
        int pk = sidx[row];
        float4 p = ps[(pk & 255) * 16 + c16];
        float4 q = qs[(pk >> 8) * 16 + c16];
        float4 v;
        v.x = (p.x + q.x) * s.x + h.x;
        v.y = (p.y + q.y) * s.y + h.y;
        v.z = (p.z + q.z) * s.z + h.z;
        v.w = (p.w + q.w) * s.w + h.w;
        v.x = fmaxf(v.x, SLOPE * v.x);
        v.y = fmaxf(v.y, SLOPE * v.y);
        v.z = fmaxf(v.z, SLOPE * v.z);
        v.w = fmaxf(v.w, SLOPE * v.w);
        *(float4*)&out[(size_t)(b*2048 + row)*256 + qt*64 + c16*4] = v;
    }
}

// ---------------- launcher ------------------------------------------------
extern "C" void kernel_launch(void* const* d_in, const int* in_sizes, int n_in,
                              void* d_out, int out_size) {
    const float* atom_features = (const float*)d_in[0];
    const float* bond_features = (const float*)d_in[1];
    const int*   atom_nl       = (const int*)  d_in[2];
    const int*   bond_nl       = (const int*)  d_in[3];
    const float* atom_W        = (const float*)d_in[4];
    const float* atom_gamma    = (const float*)d_in[6];
    const float* atom_beta     = (const float*)d_in[7];
    const float* nei_W         = (const float*)d_in[8];
    const float* nei_gamma     = (const float*)d_in[10];
    const float* nei_beta      = (const float*)d_in[11];

    float* out_atom = (float*)d_out;
    float* out_nei  = (float*)d_out + ATOM_OUT_ELEMS;

    float *pP = nullptr, *pQ = nullptr;
    cudaGetSymbolAddress((void**)&pP, g_P);
    cudaGetSymbolAddress((void**)&pQ, g_Q);

    const int smem64s = (64*FPC + 64*64 + 2*FPC) * (int)sizeof(float); // 83968
    const int smem64  = (64*FPC + 64*64) * (int)sizeof(float);         // 81920
    const int smem32  = (32*FPC + 32*64) * (int)sizeof(float);         // 40960
    const int smemNO  = (128*16 + 256*16) * 16 + 2048 * 4;             // 106496
    cudaFuncSetAttribute((const void*)gemm_kernel<64, true>,
                         cudaFuncAttributeMaxDynamicSharedMemorySize, smem64s);
    cudaFuncSetAttribute((const void*)gemm_kernel<64, false>,
                         cudaFuncAttributeMaxDynamicSharedMemorySize, smem64);
    cudaFuncSetAttribute((const void*)gemm_kernel<32, false>,
                         cudaFuncAttributeMaxDynamicSharedMemorySize, smem32);
    cudaFuncSetAttribute((const void*)nei_out_kernel,
                         cudaFuncAttributeMaxDynamicSharedMemorySize, smemNO);

    // 1) zero Sab + stat accumulators
    zero_kernel<<<8, 256>>>();

    // 2) per-batch neighbor-count histograms
    count_kernel<<<BATCH, 256>>>(atom_nl, bond_nl);

    // 3) P = A @ Wa^T, Q = B @ Wb^T (raw; bias cancels in BN)
    gemm_kernel<64, false><<<512, 256, smem64>>>(
        (const float4*)nei_W, 24, 0, (const float4*)atom_features, pP, R_ATOM / 64);
    gemm_kernel<32, false><<<592, 256, smem32>>>(
        (const float4*)nei_W, 24, 16, (const float4*)bond_features, pQ, R_BOND / 64);

    // 4) atom GEMM: raw t + stats epilogue
    gemm_kernel<64, true><<<512, 256, smem64s>>>(
        (const float4*)atom_W, 16, 0, (const float4*)atom_features,
        out_atom, R_ATOM / 64);

    // 5) cross moment over gathered pairs
    sab_kernel<<<1024, 256>>>((const float4*)atom_features,
                              (const float4*)bond_features, atom_nl, bond_nl);

    // 6) weighted column sums of P/Q -> nei 1st/2nd moments (minus cross)
    pq_stats_kernel<<<1024, 256>>>();

    // 7) scale/shift for both branches
    finalize_kernel<<<257, 256>>>(atom_gamma, atom_beta,
                                  nei_W, nei_gamma, nei_beta);

    // 8) atom normalize in place
    norm_leaky_kernel<<<512, 256>>>((float4*)out_atom, ATOM_OUT_ELEMS / 4);

    // 9) nei output: smem-cached quarters, fused normalize+leaky
    nei_out_kernel<<<BATCH * 4, 512, smemNO>>>(atom_nl, bond_nl, out_nei);
}